// round 6
// baseline (speedup 1.0000x reference)
#include <cuda_runtime.h>
#include <math.h>
#include <cstdint>

#define BB   8192
#define DVV  768
#define NE   8
#define DD   1024
#define GG   2048

// GEMM tiling: CTA 128x128, 8 warps of 32x64, BK=32, 3-stage cp.async
#define BM 128
#define BN 128
#define BK 32
#define STAGES 3
#define PADK 36
#define STAGE_FLOATS ((BM + BN) * PADK)
#define SMEM_BYTES (STAGES * STAGE_FLOATS * 4)

// ---------------------------------------------------------------------------
// Scratch (static device globals)
// ---------------------------------------------------------------------------
__device__ float g_inr[(size_t)2 * BB * DVV];     // [z][B][768] rna inputs
__device__ float g_pwT[(size_t)2 * DVV * DD];     // [z][N=1024][K=768]
__device__ float g_pbias[2 * DD];                 // [z][1024]
__device__ float g_w1T[(size_t)NE * GG * DD];     // [e][n=DD][k=GG]
__device__ float g_w2T[(size_t)NE * DD * DD];     // [e][n=DD][k=DD]
__device__ float g_combined[(size_t)BB * GG];
__device__ float g_gate[BB * NE];
__device__ float g_h[(size_t)BB * NE * DD];
__device__ float g_t[(size_t)BB * NE * DD];

// ---------------------------------------------------------------------------
// Helpers
// ---------------------------------------------------------------------------
__device__ __forceinline__ float rna_tf32(float x) {
    uint32_t u;
    asm("cvt.rna.tf32.f32 %0, %1;" : "=r"(u) : "f"(x));
    return __uint_as_float(u);
}
__device__ __forceinline__ uint32_t smem_u32(const void* p) {
    uint32_t a;
    asm("{ .reg .u64 t; cvta.to.shared.u64 t, %1; cvt.u32.u64 %0, t; }" : "=r"(a) : "l"(p));
    return a;
}
__device__ __forceinline__ void cp_async16(uint32_t dst, const float* src) {
    asm volatile("cp.async.cg.shared.global [%0], [%1], 16;" :: "r"(dst), "l"(src));
}
#define CP_COMMIT() asm volatile("cp.async.commit_group;" ::: "memory")
#define CP_WAIT(n)  asm volatile("cp.async.wait_group %0;" :: "n"(n) : "memory")

__device__ __forceinline__ void mma_tf32(float& c0, float& c1, float& c2, float& c3,
                                         uint32_t a0, uint32_t a1, uint32_t a2, uint32_t a3,
                                         uint32_t b0, uint32_t b1) {
    asm volatile(
        "mma.sync.aligned.m16n8k8.row.col.f32.tf32.tf32.f32 "
        "{%0,%1,%2,%3}, {%4,%5,%6,%7}, {%8,%9}, {%0,%1,%2,%3};\n"
        : "+f"(c0), "+f"(c1), "+f"(c2), "+f"(c3)
        : "r"(a0), "r"(a1), "r"(a2), "r"(a3), "r"(b0), "r"(b1));
}

// ---------------------------------------------------------------------------
// tf32 tensor-core GEMM: C[m,n] = act( sum_k A[m,k]*B[n,k] + bias[n] )
// CTA 128x128, warp grid 4(m) x 2(n), warp tile 32x64, 3-stage cp.async.
// mode 0: store rna(v), mode 1: store rna(gelu(v)), mode 2: store v
// colOfs total = colOfs + z*colStride (for batched projection into combined)
// ---------------------------------------------------------------------------
__global__ __launch_bounds__(256, 2)
void tf32_gemm(const float* __restrict__ A, long aBatch, int lda,
               const float* __restrict__ B, long bBatch, int ldb,
               const float* __restrict__ bias, long biasBatch,
               int K, int mode,
               float* __restrict__ C, long cBatch, int ldc,
               int colOfs, int colStride)
{
    extern __shared__ float smem[];
    const int tid  = threadIdx.x;
    const int wid  = tid >> 5;
    const int lane = tid & 31;
    const int e    = blockIdx.z;
    const int blockRow = blockIdx.y * BM;
    const int blockCol = blockIdx.x * BN;

    A    += (long)e * aBatch;
    B    += (long)e * bBatch;
    bias += (long)e * biasBatch;
    C    += (long)e * cBatch;
    const int cOfs = colOfs + e * colStride;

    const float* Ag = A + (long)blockRow * lda;
    const float* Bg = B + (long)blockCol * ldb;

    const uint32_t smem_base = smem_u32(smem);

    // warp grid: 4 (m) x 2 (n); warp tile 32x64
    const int warpRow = (wid >> 1) * 32;
    const int warpCol = (wid & 1) * 64;
    const int groupID = lane >> 2;
    const int ctig    = lane & 3;

    float acc[2][8][4];
    #pragma unroll
    for (int i = 0; i < 2; i++)
        #pragma unroll
        for (int j = 0; j < 8; j++)
            #pragma unroll
            for (int r = 0; r < 4; r++) acc[i][j][r] = 0.0f;

    const int NC = K / BK;

    // stage loader: A 1024 16B-chunks + B 1024 16B-chunks, 8/thread
    auto load_stage = [&](int stage, int chunk) {
        const int k0 = chunk * BK;
        const uint32_t aBase = smem_base + (uint32_t)(stage * STAGE_FLOATS) * 4u;
        const uint32_t bBase = aBase + (uint32_t)(BM * PADK) * 4u;
        #pragma unroll
        for (int i = 0; i < 4; i++) {
            int id = tid + i * 256;
            int m = id >> 3, kc = id & 7;
            cp_async16(aBase + (uint32_t)(m * PADK + kc * 4) * 4u,
                       Ag + (long)m * lda + k0 + kc * 4);
        }
        #pragma unroll
        for (int i = 0; i < 4; i++) {
            int id = tid + i * 256;
            int n = id >> 3, kc = id & 7;
            cp_async16(bBase + (uint32_t)(n * PADK + kc * 4) * 4u,
                       Bg + (long)n * ldb + k0 + kc * 4);
        }
        CP_COMMIT();
    };

    #pragma unroll
    for (int s = 0; s < STAGES - 1; s++) load_stage(s, s);
    CP_WAIT(STAGES - 2);
    __syncthreads();

    for (int c = 0; c < NC; c++) {
        if (c + STAGES - 1 < NC)
            load_stage((c + STAGES - 1) % STAGES, c + STAGES - 1);

        const int stage = c % STAGES;
        const uint32_t* As = reinterpret_cast<const uint32_t*>(smem + stage * STAGE_FLOATS);
        const uint32_t* Bs = As + BM * PADK;

        #pragma unroll
        for (int kk = 0; kk < 4; kk++) {
            uint32_t a[2][4], b[8][2];
            const int kb = kk * 8;
            #pragma unroll
            for (int i = 0; i < 2; i++) {
                const uint32_t* p = As + (warpRow + i * 16 + groupID) * PADK + kb + ctig;
                a[i][0] = p[0];
                a[i][1] = p[8 * PADK];
                a[i][2] = p[4];
                a[i][3] = p[8 * PADK + 4];
            }
            #pragma unroll
            for (int j = 0; j < 8; j++) {
                const uint32_t* p = Bs + (warpCol + j * 8 + groupID) * PADK + kb + ctig;
                b[j][0] = p[0];
                b[j][1] = p[4];
            }
            #pragma unroll
            for (int i = 0; i < 2; i++)
                #pragma unroll
                for (int j = 0; j < 8; j++)
                    mma_tf32(acc[i][j][0], acc[i][j][1], acc[i][j][2], acc[i][j][3],
                             a[i][0], a[i][1], a[i][2], a[i][3],
                             b[j][0], b[j][1]);
        }

        CP_WAIT(STAGES - 2);
        __syncthreads();
    }

    // epilogue
    #pragma unroll
    for (int i = 0; i < 2; i++) {
        const int r0 = blockRow + warpRow + i * 16 + groupID;
        #pragma unroll
        for (int j = 0; j < 8; j++) {
            const int gc = blockCol + warpCol + j * 8 + ctig * 2;
            const float b0 = bias[gc], b1 = bias[gc + 1];
            float v0 = acc[i][j][0] + b0;
            float v1 = acc[i][j][1] + b1;
            float v2 = acc[i][j][2] + b0;
            float v3 = acc[i][j][3] + b1;
            if (mode == 1) {
                v0 = 0.5f * v0 * (1.0f + erff(v0 * 0.70710678118654752f));
                v1 = 0.5f * v1 * (1.0f + erff(v1 * 0.70710678118654752f));
                v2 = 0.5f * v2 * (1.0f + erff(v2 * 0.70710678118654752f));
                v3 = 0.5f * v3 * (1.0f + erff(v3 * 0.70710678118654752f));
            }
            if (mode != 2) {
                v0 = rna_tf32(v0); v1 = rna_tf32(v1);
                v2 = rna_tf32(v2); v3 = rna_tf32(v3);
            }
            float* c0p = C + (long)r0 * ldc + cOfs + gc;
            float* c1p = C + (long)(r0 + 8) * ldc + cOfs + gc;
            *reinterpret_cast<float2*>(c0p) = make_float2(v0, v1);
            *reinterpret_cast<float2*>(c1p) = make_float2(v2, v3);
        }
    }
}

// ---------------------------------------------------------------------------
// Fused prep: rna-round both inputs into g_inr, pack proj biases
// ---------------------------------------------------------------------------
__global__ void prep_round_kernel(const float* __restrict__ visual,
                                  const float* __restrict__ text,
                                  const float* __restrict__ vis_b,
                                  const float* __restrict__ txt_b,
                                  float* __restrict__ inr,
                                  float* __restrict__ pbias)
{
    const long nPer = (long)BB * DVV;
    long t = (long)blockIdx.x * blockDim.x + threadIdx.x;
    if (t < 2 * DD)
        pbias[t] = (t < DD) ? vis_b[t] : txt_b[t - DD];
    long i = t * 4;
    if (i >= 2 * nPer) return;
    const float* src = (i < nPer) ? (visual + i) : (text + (i - nPer));
    float4 v = *reinterpret_cast<const float4*>(src);
    v.x = rna_tf32(v.x); v.y = rna_tf32(v.y);
    v.z = rna_tf32(v.z); v.w = rna_tf32(v.w);
    *reinterpret_cast<float4*>(inr + i) = v;
}

// ---------------------------------------------------------------------------
// W [K,N] -> WT [N,K] rna-rounded; z selects between two source pointers
// (src2 == nullptr: batched single source with stride K*N)
// ---------------------------------------------------------------------------
__global__ __launch_bounds__(256)
void transpose_round_kernel(const float* __restrict__ W0,
                            const float* __restrict__ W1,
                            float* __restrict__ WT, int K, int N)
{
    __shared__ float tile[32][33];
    const int e = blockIdx.z;
    const float* W = (W1 == nullptr) ? (W0 + (long)e * K * N)
                                     : (e == 0 ? W0 : W1);
    float* WTe = WT + (long)e * K * N;
    const int n0 = blockIdx.x * 32, k0 = blockIdx.y * 32;
    const int tx = threadIdx.x & 31, ty = threadIdx.x >> 5;

    #pragma unroll
    for (int r = 0; r < 4; r++)
        tile[ty + r * 8][tx] = W[(long)(k0 + ty + r * 8) * N + n0 + tx];
    __syncthreads();
    #pragma unroll
    for (int r = 0; r < 4; r++) {
        int n = n0 + ty + r * 8, k = k0 + tx;
        WTe[(long)n * K + k] = rna_tf32(tile[tx][ty + r * 8]);
    }
}

// ---------------------------------------------------------------------------
// Gate: one warp per row
// ---------------------------------------------------------------------------
__global__ void gate_kernel(const float* __restrict__ combined,
                            const float* __restrict__ gw,
                            const float* __restrict__ gb,
                            float* __restrict__ gate)
{
    int warp = (blockIdx.x * blockDim.x + threadIdx.x) >> 5;
    int lane = threadIdx.x & 31;
    if (warp >= BB) return;
    const float* row = combined + (long)warp * GG;

    float acc[NE];
    #pragma unroll
    for (int e = 0; e < NE; e++) acc[e] = 0.0f;

    for (int k = lane; k < GG; k += 32) {
        float x = row[k];
        const float4 w0 = *reinterpret_cast<const float4*>(gw + (long)k * NE);
        const float4 w1 = *reinterpret_cast<const float4*>(gw + (long)k * NE + 4);
        acc[0] = fmaf(x, w0.x, acc[0]);
        acc[1] = fmaf(x, w0.y, acc[1]);
        acc[2] = fmaf(x, w0.z, acc[2]);
        acc[3] = fmaf(x, w0.w, acc[3]);
        acc[4] = fmaf(x, w1.x, acc[4]);
        acc[5] = fmaf(x, w1.y, acc[5]);
        acc[6] = fmaf(x, w1.z, acc[6]);
        acc[7] = fmaf(x, w1.w, acc[7]);
    }
    #pragma unroll
    for (int e = 0; e < NE; e++)
        #pragma unroll
        for (int o = 16; o > 0; o >>= 1)
            acc[e] += __shfl_xor_sync(0xFFFFFFFFu, acc[e], o);

    float m = -1e30f;
    #pragma unroll
    for (int e = 0; e < NE; e++) { acc[e] += gb[e]; m = fmaxf(m, acc[e]); }
    float s = 0.0f;
    #pragma unroll
    for (int e = 0; e < NE; e++) { acc[e] = expf(acc[e] - m); s += acc[e]; }
    float inv = 1.0f / s;
    if (lane < NE) gate[(long)warp * NE + lane] = acc[lane] * inv;
}

// ---------------------------------------------------------------------------
// LayerNorm per (b,e) row + gated reduction over experts
// ---------------------------------------------------------------------------
__global__ __launch_bounds__(256)
void ln_reduce_kernel(const float* __restrict__ t,
                      const float* __restrict__ gate,
                      const float* __restrict__ ln_g,
                      const float* __restrict__ ln_b,
                      float* __restrict__ out)
{
    const int b = blockIdx.x;
    const int tid = threadIdx.x;
    const int wid = tid >> 5, lane = tid & 31;

    __shared__ float sm_s[8];
    __shared__ float sm_ss[8];

    float o[4] = {0.f, 0.f, 0.f, 0.f};

    for (int e = 0; e < NE; e++) {
        const float* row = t + ((long)b * NE + e) * DD;
        float4 x = *reinterpret_cast<const float4*>(row + tid * 4);
        float s  = x.x + x.y + x.z + x.w;
        float ss = x.x * x.x + x.y * x.y + x.z * x.z + x.w * x.w;
        #pragma unroll
        for (int o2 = 16; o2 > 0; o2 >>= 1) {
            s  += __shfl_xor_sync(0xFFFFFFFFu, s, o2);
            ss += __shfl_xor_sync(0xFFFFFFFFu, ss, o2);
        }
        if (lane == 0) { sm_s[wid] = s; sm_ss[wid] = ss; }
        __syncthreads();
        float ts = 0.f, tss = 0.f;
        #pragma unroll
        for (int w = 0; w < 8; w++) { ts += sm_s[w]; tss += sm_ss[w]; }
        __syncthreads();

        float mu   = ts * (1.0f / DD);
        float var  = tss * (1.0f / DD) - mu * mu;
        float rstd = rsqrtf(var + 1e-5f);
        float p    = gate[(long)b * NE + e];

        const float4 g4 = *reinterpret_cast<const float4*>(ln_g + (long)e * DD + tid * 4);
        const float4 b4 = *reinterpret_cast<const float4*>(ln_b + (long)e * DD + tid * 4);
        const float* xv = &x.x;
        const float* gv = &g4.x;
        const float* bv = &b4.x;
        #pragma unroll
        for (int j = 0; j < 4; j++) {
            float n = (xv[j] - mu) * rstd;
            o[j] = fmaf(p, fmaf(n, gv[j], bv[j]), o[j]);
        }
    }
    *reinterpret_cast<float4*>(out + (long)b * DD + tid * 4) =
        make_float4(o[0], o[1], o[2], o[3]);
}

// ---------------------------------------------------------------------------
// Launch.  Order chosen so launch #6 (ncu -s 5 -c 1) is the big expert GEMM1.
// ---------------------------------------------------------------------------
extern "C" void kernel_launch(void* const* d_in, const int* in_sizes, int n_in,
                              void* d_out, int out_size)
{
    const float* visual = (const float*)d_in[0];
    const float* text   = (const float*)d_in[1];
    const float* vis_w  = (const float*)d_in[2];
    const float* vis_b  = (const float*)d_in[3];
    const float* txt_w  = (const float*)d_in[4];
    const float* txt_b  = (const float*)d_in[5];
    const float* gate_w = (const float*)d_in[6];
    const float* gate_b = (const float*)d_in[7];
    const float* w1     = (const float*)d_in[8];
    const float* b1     = (const float*)d_in[9];
    const float* w2     = (const float*)d_in[10];
    const float* b2     = (const float*)d_in[11];
    const float* ln_g   = (const float*)d_in[12];
    const float* ln_b   = (const float*)d_in[13];
    float* out = (float*)d_out;

    float *inr, *pwT, *pbias, *w1T, *w2T, *combined, *gate, *h, *t;
    cudaGetSymbolAddress((void**)&inr, g_inr);
    cudaGetSymbolAddress((void**)&pwT, g_pwT);
    cudaGetSymbolAddress((void**)&pbias, g_pbias);
    cudaGetSymbolAddress((void**)&w1T, g_w1T);
    cudaGetSymbolAddress((void**)&w2T, g_w2T);
    cudaGetSymbolAddress((void**)&combined, g_combined);
    cudaGetSymbolAddress((void**)&gate, g_gate);
    cudaGetSymbolAddress((void**)&h, g_h);
    cudaGetSymbolAddress((void**)&t, g_t);

    cudaFuncSetAttribute(tf32_gemm, cudaFuncAttributeMaxDynamicSharedMemorySize, SMEM_BYTES);

    // 1) fused input rounding + bias pack
    {
        long n = 2L * BB * DVV;
        int blocks = (int)((n / 4 + 255) / 256);
        prep_round_kernel<<<blocks, 256>>>(visual, text, vis_b, txt_b, inr, pbias);
    }
    // 2) proj weights (both in one z=2 launch)
    transpose_round_kernel<<<dim3(DD/32, DVV/32, 2), 256>>>(vis_w, txt_w, pwT, DVV, DD);
    // 3,4) expert weights
    transpose_round_kernel<<<dim3(DD/32, GG/32, NE), 256>>>(w1, nullptr, w1T, GG, DD);
    transpose_round_kernel<<<dim3(DD/32, DD/32, NE), 256>>>(w2, nullptr, w2T, DD, DD);

    // 5) batched projection (z=2) -> combined [8192, 2048]
    {
        dim3 g(DD / BN, BB / BM, 2);
        tf32_gemm<<<g, 256, SMEM_BYTES>>>(inr, (long)BB * DVV, DVV,
                                          pwT, (long)DVV * DD, DVV,
                                          pbias, DD, DVV, 0,
                                          combined, 0, GG, 0, DD);
    }

    // 6) expert GEMM1 + GELU -> h   (this is the launch ncu profiles)
    {
        dim3 g(DD / BN, BB / BM, NE);
        tf32_gemm<<<g, 256, SMEM_BYTES>>>(combined, 0, GG,
                                          w1T, (long)GG * DD, GG,
                                          b1, DD, GG, 1,
                                          h, DD, NE * DD, 0, 0);
    }

    // 7) gate softmax
    gate_kernel<<<(BB * 32) / 256, 256>>>(combined, gate_w, gate_b, gate);

    // 8) expert GEMM2 -> t
    {
        dim3 g(DD / BN, BB / BM, NE);
        tf32_gemm<<<g, 256, SMEM_BYTES>>>(h, DD, NE * DD,
                                          w2T, (long)DD * DD, DD,
                                          b2, DD, DD, 2,
                                          t, DD, NE * DD, 0, 0);
    }

    // 9) LayerNorm + gated reduce -> out
    ln_reduce_kernel<<<BB, 256>>>(t, gate, ln_g, ln_b, out);
}